// round 13
// baseline (speedup 1.0000x reference)
#include <cuda_runtime.h>
#include <cuda_fp16.h>
#include <math.h>
#include <stdint.h>

#define BB 16
#define HH 64
#define WW 64
#define HID 12
#define MODES 16
#define LIFTC 256
#define OUTC 640
#define NPIX (BB*HH*WW)      /* 65536 */
#define HWSZ (HH*WW)         /* 4096 */
#define EPS 1e-5f
#define TAB_N 8192
#define TAB_LO (-9.0f)
#define TAB_STEP (18.0f / TAB_N)
#define TAB_INV (TAB_N / 18.0f)
#define GT_N 8192            /* gelu table: [-8, 8], step 1/512 */

// ---------------- scratch (device globals; no allocations allowed) ----------
__device__ __align__(16) float2 g_tw[64];           // (cos, sin) interleaved
__device__ float g_scale, g_shift;
__device__ float g_branch[BB];
__device__ __align__(16) float g_t0[BB*HID*HWSZ];   // 3 MB ping
__device__ __align__(16) float g_t1[BB*HID*HWSZ];   // 3 MB pong
__device__ __align__(16) float2 g_xftA[BB*HID*32*MODES];  // spectrum ping
__device__ __align__(16) float2 g_xftB[BB*HID*32*MODES];  // spectrum pong
__device__ __align__(16) __half g_q[NPIX*LIFTC];          // 32 MB, [p][k], fp16
__device__ __align__(16) __half g_bt[OUTC*LIFTC];         // 320 KB, [e][k], fp16
__device__ __align__(16) float g_tab[12 * (TAB_N + 1)];   // lifting table, CHANNEL-major
__device__ __align__(16) float g_gt[GT_N + 1];            // gelu lookup table

__device__ __forceinline__ float gelu_exact(float x) { return x * normcdff(x); }

// table gelu: linear interp on [-8,8], exact tails
__device__ __forceinline__ float gelu_tab(float a) {
    float f = fmaf(a, 512.0f, 4096.0f);
    f = fminf(fmaxf(f, 0.0f), 8191.999f);
    int i = (int)f;
    float fr = f - (float)i;
    float a0 = g_gt[i], a1 = g_gt[i + 1];
    float g = fmaf(fr, a1 - a0, a0);
    return (a >= 8.0f) ? a : g;
}

// ---------------- combined prologue ------------------------------------------
#define PRO_TAB0 0
#define PRO_TRA0 129
#define PRO_SET0 289
#define PRO_STAT 306
#define PRO_BRAN 307
#define PRO_GRID 308

__global__ __launch_bounds__(512)
void k_prolog(const float* __restrict__ x,
              const float* __restrict__ bn2_g, const float* __restrict__ bn2_b,
              const float* __restrict__ cond,
              const float* __restrict__ g1, const float* __restrict__ b1,
              const float* __restrict__ w1, const float* __restrict__ bb1,
              const float* __restrict__ w2, const float* __restrict__ bb2,
              const float* __restrict__ w3, const float* __restrict__ bb3,
              const float* __restrict__ l1w, const float* __restrict__ l1b,
              const float* __restrict__ l2w, const float* __restrict__ l2b,
              const float* __restrict__ p2w) {
    __shared__ __align__(16) char shm[36864];
    int tid = threadIdx.x;
    int blk = blockIdx.x;

    if (blk < PRO_TRA0) {
        float* s1w = (float*)shm;
        float* s1b = s1w + 256;
        float* s2w = s1b + 256;
        float* s2b = s2w + 3072;
        float* red = s2b + 16;
        if (tid < 256) { s1w[tid] = l1w[tid]; s1b[tid] = l1b[tid]; }
        for (int i = tid; i < 256 * 12; i += 512) s2w[i] = l2w[i];
        if (tid >= 256 && tid < 268) s2b[tid - 256] = l2b[tid - 256];
        __syncthreads();

        int pl = tid & 63, qd = tid >> 6;
        int pt = blk * 64 + pl;
        float s = TAB_LO + (float)pt * TAB_STEP;
        float acc[12];
#pragma unroll
        for (int e = 0; e < 12; e++) acc[e] = 0.f;
        int d0 = qd * 32;
        for (int d = d0; d < d0 + 32; d++) {
            float u = fmaf(s, s1w[d], s1b[d]);
            float gl = gelu_exact(u);
#pragma unroll
            for (int e = 0; e < 12; e++) acc[e] = fmaf(gl, s2w[d * 12 + e], acc[e]);
        }
        if (qd > 0) {
#pragma unroll
            for (int e = 0; e < 12; e++) red[((qd - 1) * 64 + pl) * 12 + e] = acc[e];
        }
        __syncthreads();
        if (qd == 0 && pt <= TAB_N) {
            float r[12];
#pragma unroll
            for (int e = 0; e < 12; e++) r[e] = acc[e] + s2b[e];
#pragma unroll
            for (int g = 0; g < 7; g++)
#pragma unroll
                for (int e = 0; e < 12; e++) r[e] += red[(g * 64 + pl) * 12 + e];
#pragma unroll
            for (int e = 0; e < 12; e++) g_tab[e * (TAB_N + 1) + pt] = r[e];
        }
    } else if (blk < PRO_SET0) {
        float (*t)[33] = (float(*)[33])shm;
        int bx = blk - PRO_TRA0;
        int e0 = (bx % 20) * 32, k0 = (bx / 20) * 32;
        int tx = tid & 31, ty = tid >> 5;
#pragma unroll
        for (int r = 0; r < 2; r++)
            t[ty + r * 16][tx] = p2w[(k0 + ty + r * 16) * OUTC + e0 + tx];
        __syncthreads();
#pragma unroll
        for (int r = 0; r < 2; r++)
            g_bt[(e0 + ty + r * 16) * 256 + k0 + tx] = __float2half_rn(t[tx][ty + r * 16]);
    } else if (blk < PRO_STAT) {
        int sb = blk - PRO_SET0;
        if (sb == 0 && tid < 64) {
            float s, c;
            sincospif((float)tid / 32.0f, &s, &c);
            g_tw[tid] = make_float2(c, s);
        }
        int idx = sb * 512 + tid;
        if (idx <= GT_N) {
            float xx = -8.0f + (float)idx * (16.0f / GT_N);
            g_gt[idx] = gelu_exact(xx);
        }
    } else if (blk == PRO_STAT) {
        double* ssum = (double*)shm;
        double* ssq = ssum + 512;
        double s = 0.0, q = 0.0;
        const float4* x4 = (const float4*)x;
        for (int i = tid; i < NPIX / 4; i += 512) {
            float4 v = x4[i];
            s += (double)v.x + (double)v.y + (double)v.z + (double)v.w;
            q += (double)v.x * v.x + (double)v.y * v.y + (double)v.z * v.z + (double)v.w * v.w;
        }
        ssum[tid] = s; ssq[tid] = q;
        __syncthreads();
        for (int o = 256; o > 0; o >>= 1) {
            if (tid < o) { ssum[tid] += ssum[tid + o]; ssq[tid] += ssq[tid + o]; }
            __syncthreads();
        }
        if (tid == 0) {
            double m = ssum[0] / (double)NPIX;
            double var = ssq[0] / (double)NPIX - m * m;
            float rstd = rsqrtf((float)var + EPS);
            float sc = bn2_g[0] * rstd;
            g_scale = sc;
            g_shift = bn2_b[0] - (float)m * sc;
        }
    } else {
        float* w1s = (float*)shm;
        float* b1s = w1s + 104;
        float* w2s = b1s + 56;
        float* b2s = w2s + 2500;
        float* w3s = b2s + 52;
        float* b3s = w3s + 52;
        float* cs  = b3s + 3;
        float* cb  = cs + 2;
        float* h1s = cb + 2;
        int w = tid >> 5, lane = tid & 31;

        if (tid < 100) w1s[tid] = w1[tid];
        if (tid >= 128 && tid < 178) b1s[tid - 128] = bb1[tid - 128];
        if (tid >= 192 && tid < 242) b2s[tid - 192] = bb2[tid - 192];
        if (tid >= 256 && tid < 306) w3s[tid - 256] = w3[tid - 256];
        if (tid == 320) b3s[0] = bb3[0];
        for (int i = tid; i < 2500; i += 512) w2s[i] = w2[i];
        if (tid < 2) {
            float m = 0.f;
            for (int b = 0; b < BB; b++) m += cond[b * 2 + tid];
            m /= (float)BB;
            float v = 0.f;
            for (int b = 0; b < BB; b++) { float d = cond[b * 2 + tid] - m; v += d * d; }
            v /= (float)BB;
            float sc = rsqrtf(v + EPS) * g1[tid];
            cs[tid] = sc;
            cb[tid] = b1[tid] - m * sc;
        }
        __syncthreads();

        float c0 = cond[w * 2 + 0] * cs[0] + cb[0];
        float c1 = cond[w * 2 + 1] * cs[1] + cb[1];
        for (int j = lane; j < 50; j += 32)
            h1s[w * 52 + j] = tanhf(c0 * w1s[j] + c1 * w1s[50 + j] + b1s[j]);
        __syncwarp();

        float part = 0.f;
        for (int j = lane; j < 50; j += 32) {
            float a = b2s[j];
#pragma unroll 10
            for (int k = 0; k < 50; k++) a = fmaf(h1s[w * 52 + k], w2s[k * 50 + j], a);
            part += tanhf(a) * w3s[j];
        }
#pragma unroll
        for (int o = 16; o > 0; o >>= 1)
            part += __shfl_down_sync(0xffffffff, part, o);
        if (lane == 0) g_branch[w] = tanhf(part + b3s[0]);
    }
}

// ---------------- fused lift + forward DFT, block per (b,c) ------------------
__global__ __launch_bounds__(512)
void k_fwd0l(const float* __restrict__ x) {
    __shared__ float ts[4096];
    __shared__ float2 xc[64 * 16];   // [h][k]
    __shared__ float2 tw[64];
    int tid = threadIdx.x;
    int bc = blockIdx.x;
    int b = bc / 12, c = bc % 12;
    if (tid < 64) tw[tid] = g_tw[tid];

    const float* tabc = g_tab + c * (TAB_N + 1);
    float sc = g_scale, sh = g_shift;
#pragma unroll
    for (int i = 0; i < 8; i++) {
        int p = tid + i * 512;
        float s = fmaf(x[b * HWSZ + p], sc, sh);
        float f = (s - TAB_LO) * TAB_INV;
        f = fminf(fmaxf(f, 0.0f), (float)TAB_N - 0.0005f);
        int i0 = (int)f;
        float fr = f - (float)i0;
        float a = tabc[i0], bb2 = tabc[i0 + 1];
        float v = fmaf(fr, bb2 - a, a);
        ts[p] = v;
        g_t0[bc * HWSZ + p] = v;
    }
    __syncthreads();

#pragma unroll
    for (int r = 0; r < 2; r++) {
        int o = tid + r * 512;
        int h = o >> 4, k = o & 15;
        float re = 0.f, im = 0.f;
#pragma unroll 8
        for (int w = 0; w < 64; w++) {
            float2 t = tw[(w * k) & 63];
            float v = ts[h * 64 + w];
            re = fmaf(v, t.x, re);
            im = fmaf(-v, t.y, im);
        }
        xc[h * 16 + k] = make_float2(re, im);
    }
    __syncthreads();

    int mi = tid >> 4, k = tid & 15;
    int m = mi + (mi >= 16 ? 32 : 0);
    float re = 0.f, im = 0.f;
#pragma unroll 8
    for (int h = 0; h < 64; h++) {
        float2 t = tw[(h * m) & 63];
        float2 v = xc[h * 16 + k];
        re += v.x * t.x + v.y * t.y;   // * e^{-i theta}
        im += v.y * t.x - v.x * t.y;
    }
    g_xftA[(bc * 32 + mi) * 16 + k] = make_float2(re, im);
}

// ---------------- layer part A: spec + invH + invW/skip/gelu -----------------
// grid = 384: block (bo, half); half owns h in [half*32, half*32+32)
__global__ __launch_bounds__(256)
void k_specinv(int lay,
               const float* __restrict__ sw1r, const float* __restrict__ sw1i,
               const float* __restrict__ sw2r, const float* __restrict__ sw2i,
               const float* __restrict__ skw_g, const float* __restrict__ skb_g) {
    const int in_flag = lay & 1;
    const float* tin = in_flag ? g_t1 : g_t0;
    float* tout = in_flag ? g_t0 : g_t1;
    const float2* xft_in = in_flag ? g_xftB : g_xftA;

    __shared__ float2 sy[32 * 16];     // spec output  [mi][k]
    __shared__ float2 Ys[32 * 16];     // invH output for this half [hh][k]
    __shared__ float2 tw[64];
    __shared__ float skw[12];
    __shared__ float skb;

    int tid = threadIdx.x;
    int blk = blockIdx.x;
    int half = blk & 1, bo = blk >> 1;
    int b = bo / 12, o = bo % 12;
    int hbase = half * 32;
    if (tid < 64) tw[tid] = g_tw[tid];
    if (tid >= 64 && tid < 76) skw[tid - 64] = skw_g[((lay * 12 + (tid - 64)) * 12) + o];
    if (tid == 76) skb = skb_g[lay * 12 + o];

    // ---- stage 1: spectral mix (2 outputs per thread, duplicated per half) --
#pragma unroll
    for (int r = 0; r < 2; r++) {
        int idx = tid + r * 256;
        int k = idx & 15, mi = idx >> 4;
        const float* wr = (mi < 16) ? sw1r : sw2r;
        const float* wi = (mi < 16) ? sw1i : sw2i;
        int mr = (mi < 16) ? mi : mi - 16;
        float yr = 0.f, yi = 0.f;
#pragma unroll
        for (int c = 0; c < 12; c++) {
            float2 xv = xft_in[((b * 12 + c) * 32 + mi) * 16 + k];
            int off = (((lay * 12 + c) * 12 + o) * 16 + mr) * 16 + k;
            float wre = wr[off], wim = wi[off];
            yr += xv.x * wre - xv.y * wim;
            yi += xv.x * wim + xv.y * wre;
        }
        sy[idx] = make_float2(yr, yi);
    }
    __syncthreads();

    // ---- stage 2: inverse H-DFT for 32 h rows (2 outputs/thread, shared sy) -
    {
        int k = tid & 15, hh0 = tid >> 4;   // hh0 in [0,16)
        int ha = hbase + hh0, hb = ha + 16;
        float2 acc0 = {0, 0}, acc1 = {0, 0};
#pragma unroll 8
        for (int mi = 0; mi < 32; mi++) {
            int m = mi + (mi >= 16 ? 32 : 0);
            float2 v = sy[mi * 16 + k];
            float2 ta = tw[(ha * m) & 63];
            float2 tb = tw[(hb * m) & 63];
            acc0.x += v.x * ta.x - v.y * ta.y;   // * e^{+i theta}
            acc0.y += v.x * ta.y + v.y * ta.x;
            acc1.x += v.x * tb.x - v.y * tb.y;
            acc1.y += v.x * tb.y + v.y * tb.x;
        }
        Ys[hh0 * 16 + k] = acc0;
        Ys[(hh0 + 16) * 16 + k] = acc1;
    }
    __syncthreads();

    // ---- stage 3: inverse W-DFT + skip conv (+ gelu), 8 px per thread -------
    {
        int w = tid & 63, hg = tid >> 6;   // hg in [0,4)
        float2 twk[15];
#pragma unroll
        for (int k = 1; k < 16; k++) twk[k - 1] = tw[(w * k) & 63];
#pragma unroll 2
        for (int i = 0; i < 8; i++) {
            int hh = hg * 8 + i;           // local row in [0,32)
            int h = hbase + hh;
            const float2* yr = &Ys[hh * 16];
            float v = yr[0].x;    // k=0: imaginary part discarded by irfft
#pragma unroll
            for (int k = 1; k < 16; k++)
                v += 2.f * (yr[k].x * twk[k - 1].x - yr[k].y * twk[k - 1].y);
            v *= (1.0f / 4096.0f);
            float sk = skb;
#pragma unroll
            for (int c = 0; c < 12; c++)
                sk = fmaf(tin[(b * 12 + c) * HWSZ + h * 64 + w], skw[c], sk);
            float rres = v + sk;
            if (lay < 3) rres = gelu_tab(rres);
            tout[(b * 12 + o) * HWSZ + h * 64 + w] = rres;
        }
    }
}

// ---------------- layer part B: forward DFT t -> xft, block per (b,c) --------
__global__ __launch_bounds__(512)
void k_fwd(int lay) {
    const int in_flag = lay & 1;
    const float* tnow = in_flag ? g_t0 : g_t1;          // tout of part A
    float2* xft_out = in_flag ? g_xftA : g_xftB;

    __shared__ float ts[4096];
    __shared__ float2 xc[64 * 16];   // [h][k]
    __shared__ float2 tw[64];
    int tid = threadIdx.x;
    int bc = blockIdx.x;
    if (tid < 64) tw[tid] = g_tw[tid];
#pragma unroll
    for (int i = 0; i < 2; i++)
        *(float4*)&ts[(tid + i * 512) * 4] = *(const float4*)&tnow[bc * HWSZ + (tid + i * 512) * 4];
    __syncthreads();

#pragma unroll
    for (int r = 0; r < 2; r++) {
        int o = tid + r * 512;
        int h = o >> 4, k = o & 15;
        float re = 0.f, im = 0.f;
#pragma unroll 8
        for (int w = 0; w < 64; w++) {
            float2 t = tw[(w * k) & 63];
            float v = ts[h * 64 + w];
            re = fmaf(v, t.x, re);
            im = fmaf(-v, t.y, im);
        }
        xc[h * 16 + k] = make_float2(re, im);
    }
    __syncthreads();

    int mi = tid >> 4, k = tid & 15;
    int m = mi + (mi >= 16 ? 32 : 0);
    float re = 0.f, im = 0.f;
#pragma unroll 8
    for (int h = 0; h < 64; h++) {
        float2 t = tw[(h * m) & 63];
        float2 v = xc[h * 16 + k];
        re += v.x * t.x + v.y * t.y;   // * e^{-i theta}
        im += v.y * t.x - v.x * t.y;
    }
    xft_out[(bc * 32 + mi) * 16 + k] = make_float2(re, im);
}

// ---------------- projection pass 1: 12 -> 256 gelu, q[p][k] fp16 ------------
__global__ void k_proj1(const float* __restrict__ p1w, const float* __restrict__ p1b) {
    __shared__ float w1s[12 * 256];
    __shared__ float b1s[256];
    int tid = threadIdx.x;
    int wid = tid >> 5, lid = tid & 31;
    if (tid < 256) b1s[tid] = p1b[tid];
    for (int i = tid; i < 12 * 256; i += 256) w1s[i] = p1w[i];
    __syncthreads();

    int p = blockIdx.x * 8 + wid;
    int b = p >> 12, hw = p & 4095;
    float tv[12];
#pragma unroll
    for (int c = 0; c < 12; c++) tv[c] = g_t0[(b * 12 + c) * HWSZ + hw];

#pragma unroll
    for (int r = 0; r < 2; r++) {
        int jb = r * 128 + lid * 4;
        float f[4];
#pragma unroll
        for (int jj = 0; jj < 4; jj++) {
            int j = jb + jj;
            float a = b1s[j];
#pragma unroll
            for (int c = 0; c < 12; c++) a = fmaf(tv[c], w1s[c * 256 + j], a);
            f[jj] = gelu_tab(a);
        }
        __half2 h01 = __floats2half2_rn(f[0], f[1]);
        __half2 h23 = __floats2half2_rn(f[2], f[3]);
        uint2 pk;
        pk.x = *(uint32_t*)&h01;
        pk.y = *(uint32_t*)&h23;
        *(uint2*)&g_q[(size_t)p * 256 + jb] = pk;
    }
}

// ---------------- projection pass 2: mma.sync fp16 GEMM 65536x640x256 --------
#define PADK 40        /* halves per smem row (80B), conflict-free */
#define STAGEH (2 * 128 * PADK)   /* halves per stage (A + B) */
#define NSTAGE 3

__device__ __forceinline__ void mma16n8k16(float* c, const uint32_t* a, const uint32_t* b) {
    asm volatile(
        "mma.sync.aligned.m16n8k16.row.col.f32.f16.f16.f32 "
        "{%0,%1,%2,%3}, {%4,%5,%6,%7}, {%8,%9}, {%0,%1,%2,%3};"
        : "+f"(c[0]), "+f"(c[1]), "+f"(c[2]), "+f"(c[3])
        : "r"(a[0]), "r"(a[1]), "r"(a[2]), "r"(a[3]), "r"(b[0]), "r"(b[1]));
}

__global__ __launch_bounds__(256, 2)
void k_gemm_mma(const float* __restrict__ p2b, float* __restrict__ out) {
    extern __shared__ __half smh[];
    __shared__ float sPb[128];
    int tid = threadIdx.x;
    int wid = tid >> 5, lane = tid & 31;
    int tig = lane & 3, grp = lane >> 2;
    int wm = wid & 1, wn = wid >> 1;         // warp tile: 64 rows x 32 cols
    int n0 = blockIdx.x * 128;
    int m0 = blockIdx.y * 128;
    if (tid < 128) sPb[tid] = p2b[n0 + tid];

    const __half* Aop = g_q + (size_t)m0 * 256;
    const __half* Bop = g_bt + (size_t)n0 * 256;

    float acc[4][4][4];
#pragma unroll
    for (int i = 0; i < 4; i++)
#pragma unroll
        for (int j = 0; j < 4; j++)
#pragma unroll
            for (int r = 0; r < 4; r++) acc[i][j][r] = 0.f;

#define PREFETCH(ch) do {                                                     \
    int st_ = (ch) % NSTAGE;                                                  \
    __half* Ab_ = smh + st_ * STAGEH;                                         \
    __half* Bb_ = Ab_ + 128 * PADK;                                           \
    int k0_ = (ch) * 32;                                                      \
    _Pragma("unroll")                                                         \
    for (int it = 0; it < 2; it++) {                                          \
        int fi = tid + it * 256;              /* 0..511 */                    \
        int row = fi >> 2, c8 = (fi & 3) * 8;                                 \
        uint32_t da = (uint32_t)__cvta_generic_to_shared(Ab_ + row * PADK + c8); \
        const __half* ga = Aop + (size_t)row * 256 + k0_ + c8;                \
        asm volatile("cp.async.cg.shared.global [%0], [%1], 16;" :: "r"(da), "l"(ga)); \
        uint32_t db = (uint32_t)__cvta_generic_to_shared(Bb_ + row * PADK + c8); \
        const __half* gb = Bop + (size_t)row * 256 + k0_ + c8;                \
        asm volatile("cp.async.cg.shared.global [%0], [%1], 16;" :: "r"(db), "l"(gb)); \
    }                                                                         \
    asm volatile("cp.async.commit_group;" ::: "memory");                      \
} while (0)

    PREFETCH(0);
    PREFETCH(1);

    for (int ch = 0; ch < 8; ch++) {
        if (ch < 7) {
            asm volatile("cp.async.wait_group 1;" ::: "memory");
        } else {
            asm volatile("cp.async.wait_group 0;" ::: "memory");
        }
        __syncthreads();
        const __half* Ab = smh + (ch % NSTAGE) * STAGEH;
        const __half* Bb = Ab + 128 * PADK;

#pragma unroll
        for (int kk = 0; kk < 2; kk++) {      // two k16 steps per 32-chunk
            int kb = kk * 16;
            uint32_t af[4][4], bf[4][2];
#pragma unroll
            for (int mt = 0; mt < 4; mt++) {
                int r0 = wm * 64 + mt * 16 + grp;
                af[mt][0] = *(const uint32_t*)&Ab[r0 * PADK + kb + tig * 2];
                af[mt][1] = *(const uint32_t*)&Ab[(r0 + 8) * PADK + kb + tig * 2];
                af[mt][2] = *(const uint32_t*)&Ab[r0 * PADK + kb + tig * 2 + 8];
                af[mt][3] = *(const uint32_t*)&Ab[(r0 + 8) * PADK + kb + tig * 2 + 8];
            }
#pragma unroll
            for (int nt = 0; nt < 4; nt++) {
                int e = wn * 32 + nt * 8 + grp;
                bf[nt][0] = *(const uint32_t*)&Bb[e * PADK + kb + tig * 2];
                bf[nt][1] = *(const uint32_t*)&Bb[e * PADK + kb + tig * 2 + 8];
            }
#pragma unroll
            for (int mt = 0; mt < 4; mt++)
#pragma unroll
                for (int nt = 0; nt < 4; nt++)
                    mma16n8k16(acc[mt][nt], af[mt], bf[nt]);
        }
        if (ch + 2 < 8) PREFETCH(ch + 2);
    }

    // epilogue: (acc + bias) * branch
    float br = g_branch[m0 >> 12];
#pragma unroll
    for (int mt = 0; mt < 4; mt++) {
        int row0 = m0 + wm * 64 + mt * 16 + grp;
        int row1 = row0 + 8;
        float* o0 = out + (size_t)(row0 >> 6) * (OUTC * 64) + (row0 & 63);
        float* o1 = out + (size_t)(row1 >> 6) * (OUTC * 64) + (row1 & 63);
#pragma unroll
        for (int nt = 0; nt < 4; nt++) {
            int el = wn * 32 + nt * 8 + 2 * tig;     // local e in [0,128)
            int e = n0 + el;
            float b0 = sPb[el], b1 = sPb[el + 1];
            __stcs(o0 + (size_t)e * 64,       (acc[mt][nt][0] + b0) * br);
            __stcs(o0 + (size_t)(e + 1) * 64, (acc[mt][nt][1] + b1) * br);
            __stcs(o1 + (size_t)e * 64,       (acc[mt][nt][2] + b0) * br);
            __stcs(o1 + (size_t)(e + 1) * 64, (acc[mt][nt][3] + b1) * br);
        }
    }
#undef PREFETCH
}

#define GEMM_SMEM (NSTAGE * STAGEH * 2)   /* 61440 bytes */

// ---------------- launch ------------------------------------------------------
extern "C" void kernel_launch(void* const* d_in, const int* in_sizes, int n_in,
                              void* d_out, int out_size) {
    const float* x     = (const float*)d_in[0];
    const float* cond  = (const float*)d_in[1];
    const float* bn2_g = (const float*)d_in[2];
    const float* bn2_b = (const float*)d_in[3];
    const float* bn1_g = (const float*)d_in[4];
    const float* bn1_b = (const float*)d_in[5];
    const float* b_w1  = (const float*)d_in[6];
    const float* b_b1  = (const float*)d_in[7];
    const float* b_w2  = (const float*)d_in[8];
    const float* b_b2  = (const float*)d_in[9];
    const float* b_w3  = (const float*)d_in[10];
    const float* b_b3  = (const float*)d_in[11];
    const float* l1_w  = (const float*)d_in[12];
    const float* l1_b  = (const float*)d_in[13];
    const float* l2_w  = (const float*)d_in[14];
    const float* l2_b  = (const float*)d_in[15];
    const float* sw1r  = (const float*)d_in[16];
    const float* sw1i  = (const float*)d_in[17];
    const float* sw2r  = (const float*)d_in[18];
    const float* sw2i  = (const float*)d_in[19];
    const float* sk_w  = (const float*)d_in[20];
    const float* sk_b  = (const float*)d_in[21];
    const float* p1_w  = (const float*)d_in[22];
    const float* p1_b  = (const float*)d_in[23];
    const float* p2_w  = (const float*)d_in[24];
    const float* p2_b  = (const float*)d_in[25];
    float* out = (float*)d_out;

    cudaFuncSetAttribute(k_gemm_mma, cudaFuncAttributeMaxDynamicSharedMemorySize, GEMM_SMEM);

    k_prolog<<<PRO_GRID, 512>>>(x, bn2_g, bn2_b, cond, bn1_g, bn1_b,
                                b_w1, b_b1, b_w2, b_b2, b_w3, b_b3,
                                l1_w, l1_b, l2_w, l2_b, p2_w);

    k_fwd0l<<<BB * HID, 512>>>(x);
    for (int lay = 0; lay < 4; lay++) {
        k_specinv<<<BB * HID * 2, 256>>>(lay, sw1r, sw1i, sw2r, sw2i, sk_w, sk_b);
        if (lay < 3) k_fwd<<<BB * HID, 512>>>(lay);
    }

    k_proj1<<<NPIX / 8, 256>>>(p1_w, p1_b);

    dim3 gg(OUTC / 128, NPIX / 128);
    k_gemm_mma<<<gg, 256, GEMM_SMEM>>>(p2_b, out);
}

// round 14
// speedup vs baseline: 1.0353x; 1.0353x over previous
#include <cuda_runtime.h>
#include <cuda_fp16.h>
#include <math.h>
#include <stdint.h>

#define BB 16
#define HH 64
#define WW 64
#define HID 12
#define MODES 16
#define LIFTC 256
#define OUTC 640
#define NPIX (BB*HH*WW)      /* 65536 */
#define HWSZ (HH*WW)         /* 4096 */
#define EPS 1e-5f
#define TAB_N 8192
#define TAB_LO (-9.0f)
#define TAB_STEP (18.0f / TAB_N)
#define TAB_INV (TAB_N / 18.0f)
#define GT_N 8192            /* gelu table: [-8, 8], step 1/512 */

// ---------------- scratch (device globals; no allocations allowed) ----------
__device__ __align__(16) float2 g_tw[64];           // (cos, sin) interleaved
__device__ float g_scale, g_shift;
__device__ float g_branch[BB];
__device__ __align__(16) float g_t0[BB*HID*HWSZ];   // 3 MB ping
__device__ __align__(16) float g_t1[BB*HID*HWSZ];   // 3 MB pong
__device__ __align__(16) float2 g_xftA[BB*HID*32*MODES];  // spectrum ping
__device__ __align__(16) float2 g_xftB[BB*HID*32*MODES];  // spectrum pong
__device__ __align__(16) __half g_q[NPIX*LIFTC];          // 32 MB, [p][k], fp16
__device__ __align__(16) __half g_bt[OUTC*LIFTC];         // 320 KB, [e][k], fp16
__device__ __align__(16) float g_tab[12 * (TAB_N + 1)];   // lifting table, CHANNEL-major
__device__ __align__(16) float g_gt[GT_N + 1];            // gelu lookup table

__device__ __forceinline__ float gelu_exact(float x) { return x * normcdff(x); }

// table gelu: linear interp on [-8,8], exact tails
__device__ __forceinline__ float gelu_tab(float a) {
    float f = fmaf(a, 512.0f, 4096.0f);
    f = fminf(fmaxf(f, 0.0f), 8191.999f);
    int i = (int)f;
    float fr = f - (float)i;
    float a0 = g_gt[i], a1 = g_gt[i + 1];
    float g = fmaf(fr, a1 - a0, a0);
    return (a >= 8.0f) ? a : g;
}

// ---------------- combined prologue ------------------------------------------
#define PRO_TAB0 0
#define PRO_TRA0 129
#define PRO_SET0 289
#define PRO_STAT 306
#define PRO_BRAN 307
#define PRO_GRID 308

__global__ __launch_bounds__(512)
void k_prolog(const float* __restrict__ x,
              const float* __restrict__ bn2_g, const float* __restrict__ bn2_b,
              const float* __restrict__ cond,
              const float* __restrict__ g1, const float* __restrict__ b1,
              const float* __restrict__ w1, const float* __restrict__ bb1,
              const float* __restrict__ w2, const float* __restrict__ bb2,
              const float* __restrict__ w3, const float* __restrict__ bb3,
              const float* __restrict__ l1w, const float* __restrict__ l1b,
              const float* __restrict__ l2w, const float* __restrict__ l2b,
              const float* __restrict__ p2w) {
    __shared__ __align__(16) char shm[36864];
    int tid = threadIdx.x;
    int blk = blockIdx.x;

    if (blk < PRO_TRA0) {
        float* s1w = (float*)shm;
        float* s1b = s1w + 256;
        float* s2w = s1b + 256;
        float* s2b = s2w + 3072;
        float* red = s2b + 16;
        if (tid < 256) { s1w[tid] = l1w[tid]; s1b[tid] = l1b[tid]; }
        for (int i = tid; i < 256 * 12; i += 512) s2w[i] = l2w[i];
        if (tid >= 256 && tid < 268) s2b[tid - 256] = l2b[tid - 256];
        __syncthreads();

        int pl = tid & 63, qd = tid >> 6;
        int pt = blk * 64 + pl;
        float s = TAB_LO + (float)pt * TAB_STEP;
        float acc[12];
#pragma unroll
        for (int e = 0; e < 12; e++) acc[e] = 0.f;
        int d0 = qd * 32;
        for (int d = d0; d < d0 + 32; d++) {
            float u = fmaf(s, s1w[d], s1b[d]);
            float gl = gelu_exact(u);
#pragma unroll
            for (int e = 0; e < 12; e++) acc[e] = fmaf(gl, s2w[d * 12 + e], acc[e]);
        }
        if (qd > 0) {
#pragma unroll
            for (int e = 0; e < 12; e++) red[((qd - 1) * 64 + pl) * 12 + e] = acc[e];
        }
        __syncthreads();
        if (qd == 0 && pt <= TAB_N) {
            float r[12];
#pragma unroll
            for (int e = 0; e < 12; e++) r[e] = acc[e] + s2b[e];
#pragma unroll
            for (int g = 0; g < 7; g++)
#pragma unroll
                for (int e = 0; e < 12; e++) r[e] += red[(g * 64 + pl) * 12 + e];
#pragma unroll
            for (int e = 0; e < 12; e++) g_tab[e * (TAB_N + 1) + pt] = r[e];
        }
    } else if (blk < PRO_SET0) {
        float (*t)[33] = (float(*)[33])shm;
        int bx = blk - PRO_TRA0;
        int e0 = (bx % 20) * 32, k0 = (bx / 20) * 32;
        int tx = tid & 31, ty = tid >> 5;
#pragma unroll
        for (int r = 0; r < 2; r++)
            t[ty + r * 16][tx] = p2w[(k0 + ty + r * 16) * OUTC + e0 + tx];
        __syncthreads();
#pragma unroll
        for (int r = 0; r < 2; r++)
            g_bt[(e0 + ty + r * 16) * 256 + k0 + tx] = __float2half_rn(t[tx][ty + r * 16]);
    } else if (blk < PRO_STAT) {
        int sb = blk - PRO_SET0;
        if (sb == 0 && tid < 64) {
            float s, c;
            sincospif((float)tid / 32.0f, &s, &c);
            g_tw[tid] = make_float2(c, s);
        }
        int idx = sb * 512 + tid;
        if (idx <= GT_N) {
            float xx = -8.0f + (float)idx * (16.0f / GT_N);
            g_gt[idx] = gelu_exact(xx);
        }
    } else if (blk == PRO_STAT) {
        double* ssum = (double*)shm;
        double* ssq = ssum + 512;
        double s = 0.0, q = 0.0;
        const float4* x4 = (const float4*)x;
        for (int i = tid; i < NPIX / 4; i += 512) {
            float4 v = x4[i];
            s += (double)v.x + (double)v.y + (double)v.z + (double)v.w;
            q += (double)v.x * v.x + (double)v.y * v.y + (double)v.z * v.z + (double)v.w * v.w;
        }
        ssum[tid] = s; ssq[tid] = q;
        __syncthreads();
        for (int o = 256; o > 0; o >>= 1) {
            if (tid < o) { ssum[tid] += ssum[tid + o]; ssq[tid] += ssq[tid + o]; }
            __syncthreads();
        }
        if (tid == 0) {
            double m = ssum[0] / (double)NPIX;
            double var = ssq[0] / (double)NPIX - m * m;
            float rstd = rsqrtf((float)var + EPS);
            float sc = bn2_g[0] * rstd;
            g_scale = sc;
            g_shift = bn2_b[0] - (float)m * sc;
        }
    } else {
        float* w1s = (float*)shm;
        float* b1s = w1s + 104;
        float* w2s = b1s + 56;
        float* b2s = w2s + 2500;
        float* w3s = b2s + 52;
        float* b3s = w3s + 52;
        float* cs  = b3s + 3;
        float* cb  = cs + 2;
        float* h1s = cb + 2;
        int w = tid >> 5, lane = tid & 31;

        if (tid < 100) w1s[tid] = w1[tid];
        if (tid >= 128 && tid < 178) b1s[tid - 128] = bb1[tid - 128];
        if (tid >= 192 && tid < 242) b2s[tid - 192] = bb2[tid - 192];
        if (tid >= 256 && tid < 306) w3s[tid - 256] = w3[tid - 256];
        if (tid == 320) b3s[0] = bb3[0];
        for (int i = tid; i < 2500; i += 512) w2s[i] = w2[i];
        if (tid < 2) {
            float m = 0.f;
            for (int b = 0; b < BB; b++) m += cond[b * 2 + tid];
            m /= (float)BB;
            float v = 0.f;
            for (int b = 0; b < BB; b++) { float d = cond[b * 2 + tid] - m; v += d * d; }
            v /= (float)BB;
            float sc = rsqrtf(v + EPS) * g1[tid];
            cs[tid] = sc;
            cb[tid] = b1[tid] - m * sc;
        }
        __syncthreads();

        float c0 = cond[w * 2 + 0] * cs[0] + cb[0];
        float c1 = cond[w * 2 + 1] * cs[1] + cb[1];
        for (int j = lane; j < 50; j += 32)
            h1s[w * 52 + j] = tanhf(c0 * w1s[j] + c1 * w1s[50 + j] + b1s[j]);
        __syncwarp();

        float part = 0.f;
        for (int j = lane; j < 50; j += 32) {
            float a = b2s[j];
#pragma unroll 10
            for (int k = 0; k < 50; k++) a = fmaf(h1s[w * 52 + k], w2s[k * 50 + j], a);
            part += tanhf(a) * w3s[j];
        }
#pragma unroll
        for (int o = 16; o > 0; o >>= 1)
            part += __shfl_down_sync(0xffffffff, part, o);
        if (lane == 0) g_branch[w] = tanhf(part + b3s[0]);
    }
}

// ---------------- fused lift + forward DFT, block per (b,c) ------------------
__global__ __launch_bounds__(512)
void k_fwd0l(const float* __restrict__ x) {
    __shared__ float ts[4096];
    __shared__ float2 xc[64 * 16];   // [h][k]
    __shared__ float2 tw[64];
    int tid = threadIdx.x;
    int bc = blockIdx.x;
    int b = bc / 12, c = bc % 12;
    if (tid < 64) tw[tid] = g_tw[tid];

    const float* tabc = g_tab + c * (TAB_N + 1);
    float sc = g_scale, sh = g_shift;
#pragma unroll
    for (int i = 0; i < 8; i++) {
        int p = tid + i * 512;
        float s = fmaf(x[b * HWSZ + p], sc, sh);
        float f = (s - TAB_LO) * TAB_INV;
        f = fminf(fmaxf(f, 0.0f), (float)TAB_N - 0.0005f);
        int i0 = (int)f;
        float fr = f - (float)i0;
        float a = tabc[i0], bb2 = tabc[i0 + 1];
        float v = fmaf(fr, bb2 - a, a);
        ts[p] = v;
        g_t0[bc * HWSZ + p] = v;
    }
    __syncthreads();

#pragma unroll
    for (int r = 0; r < 2; r++) {
        int o = tid + r * 512;
        int h = o >> 4, k = o & 15;
        float re = 0.f, im = 0.f;
#pragma unroll 8
        for (int w = 0; w < 64; w++) {
            float2 t = tw[(w * k) & 63];
            float v = ts[h * 64 + w];
            re = fmaf(v, t.x, re);
            im = fmaf(-v, t.y, im);
        }
        xc[h * 16 + k] = make_float2(re, im);
    }
    __syncthreads();

    int mi = tid >> 4, k = tid & 15;
    int m = mi + (mi >= 16 ? 32 : 0);
    float re = 0.f, im = 0.f;
#pragma unroll 8
    for (int h = 0; h < 64; h++) {
        float2 t = tw[(h * m) & 63];
        float2 v = xc[h * 16 + k];
        re += v.x * t.x + v.y * t.y;   // * e^{-i theta}
        im += v.y * t.x - v.x * t.y;
    }
    g_xftA[(bc * 32 + mi) * 16 + k] = make_float2(re, im);
}

// ---------------- fused layer: spec + invH + invW/skip/gelu + fwdW + fwdH ----
// 256 threads/block; quarter-turn twiddle identity; Ys prescaled by irfft norm
__global__ __launch_bounds__(256)
void k_layer(int lay,
             const float* __restrict__ sw1r, const float* __restrict__ sw1i,
             const float* __restrict__ sw2r, const float* __restrict__ sw2i,
             const float* __restrict__ skw_g, const float* __restrict__ skb_g) {
    const int in_flag = lay & 1;
    const float* tin = in_flag ? g_t1 : g_t0;
    float* tout = in_flag ? g_t0 : g_t1;
    const float2* xft_in = in_flag ? g_xftB : g_xftA;
    float2* xft_out = in_flag ? g_xftA : g_xftB;

    __shared__ float2 sy[32 * 16];     // spec output  [mi][k]
    __shared__ float2 Ys[64 * 16];     // invH output  [h][k], prescaled
    __shared__ float ts[4096];         // spatial field
    __shared__ float2 xc[64 * 16];     // fwdW output  [h][k]
    __shared__ float2 tw[64];
    __shared__ float skw[12];
    __shared__ float skb;

    int tid = threadIdx.x;
    int bo = blockIdx.x;
    int b = bo / 12, o = bo % 12;
    if (tid < 64) tw[tid] = g_tw[tid];
    if (tid >= 64 && tid < 76) skw[tid - 64] = skw_g[((lay * 12 + (tid - 64)) * 12) + o];
    if (tid == 76) skb = skb_g[lay * 12 + o];

    // ---- stage 1: spectral mix (2 outputs per thread) ----
#pragma unroll
    for (int r = 0; r < 2; r++) {
        int idx = tid + r * 256;
        int k = idx & 15, mi = idx >> 4;
        const float* wr = (mi < 16) ? sw1r : sw2r;
        const float* wi = (mi < 16) ? sw1i : sw2i;
        int mr = (mi < 16) ? mi : mi - 16;
        float yr = 0.f, yi = 0.f;
#pragma unroll
        for (int c = 0; c < 12; c++) {
            float2 xv = xft_in[((b * 12 + c) * 32 + mi) * 16 + k];
            int off = (((lay * 12 + c) * 12 + o) * 16 + mr) * 16 + k;
            float wre = wr[off], wim = wi[off];
            yr += xv.x * wre - xv.y * wim;
            yi += xv.x * wim + xv.y * wre;
        }
        sy[idx] = make_float2(yr, yi);
    }
    __syncthreads();

    // ---- stage 2: inverse H-DFT, 4 outputs/thread via i^q rotations,
    //      prescaled by (k==0 ? 1 : 2)/4096 for stage 3 ----
    {
        int k = tid & 15, h0 = tid >> 4;       // h0 in [0,16)
        float s3 = (k == 0) ? (1.0f / 4096.0f) : (2.0f / 4096.0f);
        float2 acc0 = {0,0}, acc1 = {0,0}, acc2 = {0,0}, acc3 = {0,0};
#pragma unroll
        for (int mib = 0; mib < 32; mib += 4) {
#pragma unroll
            for (int j = 0; j < 4; j++) {
                int mi = mib + j;
                int m = mi + (mi >= 16 ? 32 : 0);
                float2 v = sy[mi * 16 + k];
                float2 t = tw[(h0 * m) & 63];
                float pr = v.x * t.x - v.y * t.y;   // v * e^{+i theta0}
                float pi = v.x * t.y + v.y * t.x;
                acc0.x += pr; acc0.y += pi;
                if (j == 0) {
                    acc1.x += pr; acc1.y += pi;
                    acc2.x += pr; acc2.y += pi;
                    acc3.x += pr; acc3.y += pi;
                } else if (j == 1) {                 // q = r
                    acc1.x -= pi; acc1.y += pr;
                    acc2.x -= pr; acc2.y -= pi;
                    acc3.x += pi; acc3.y -= pr;
                } else if (j == 2) {                 // q = 2r & 3
                    acc1.x -= pr; acc1.y -= pi;
                    acc2.x += pr; acc2.y += pi;
                    acc3.x -= pr; acc3.y -= pi;
                } else {                             // q = 3r & 3
                    acc1.x += pi; acc1.y -= pr;
                    acc2.x -= pr; acc2.y -= pi;
                    acc3.x -= pi; acc3.y += pr;
                }
            }
        }
        Ys[h0 * 16 + k] = make_float2(acc0.x * s3, acc0.y * s3);
        Ys[(h0 + 16) * 16 + k] = make_float2(acc1.x * s3, acc1.y * s3);
        Ys[(h0 + 32) * 16 + k] = make_float2(acc2.x * s3, acc2.y * s3);
        Ys[(h0 + 48) * 16 + k] = make_float2(acc3.x * s3, acc3.y * s3);
    }
    __syncthreads();

    // ---- stage 3: inverse W-DFT + skip conv (+ gelu), 16 px per thread ----
    // Ys prescaled: v = yr0.x + sum_k (yr.x*twc - yr.y*tws), pure FMA chain
    {
        int w = tid & 63, hg = tid >> 6;   // hg in [0,4)
        float2 twk[15];
#pragma unroll
        for (int k = 1; k < 16; k++) twk[k - 1] = tw[(w * k) & 63];
#pragma unroll 2
        for (int i = 0; i < 16; i++) {
            int h = hg * 16 + i;
            const float2* yr = &Ys[h * 16];
            float v = yr[0].x;    // k=0: imaginary part discarded by irfft
#pragma unroll
            for (int k = 1; k < 16; k++) {
                v = fmaf(yr[k].x, twk[k - 1].x, v);
                v = fmaf(-yr[k].y, twk[k - 1].y, v);
            }
            float sk = skb;
#pragma unroll
            for (int c = 0; c < 12; c++)
                sk = fmaf(tin[(b * 12 + c) * HWSZ + h * 64 + w], skw[c], sk);
            float rres = v + sk;
            if (lay < 3) {
                rres = gelu_tab(rres);
                ts[h * 64 + w] = rres;
            }
            tout[(b * 12 + o) * HWSZ + h * 64 + w] = rres;
        }
    }
    if (lay == 3) return;
    __syncthreads();

    // ---- stage 4: forward W-DFT, 4 outputs/thread sharing twiddles ----
    {
        int k = tid & 15, h0 = tid >> 4;
        float re0 = 0, im0 = 0, re1 = 0, im1 = 0, re2 = 0, im2 = 0, re3 = 0, im3 = 0;
#pragma unroll 8
        for (int w = 0; w < 64; w++) {
            float2 t = tw[(w * k) & 63];
            float v0 = ts[h0 * 64 + w];
            float v1 = ts[(h0 + 16) * 64 + w];
            float v2 = ts[(h0 + 32) * 64 + w];
            float v3 = ts[(h0 + 48) * 64 + w];
            re0 = fmaf(v0, t.x, re0); im0 = fmaf(-v0, t.y, im0);
            re1 = fmaf(v1, t.x, re1); im1 = fmaf(-v1, t.y, im1);
            re2 = fmaf(v2, t.x, re2); im2 = fmaf(-v2, t.y, im2);
            re3 = fmaf(v3, t.x, re3); im3 = fmaf(-v3, t.y, im3);
        }
        xc[h0 * 16 + k] = make_float2(re0, im0);
        xc[(h0 + 16) * 16 + k] = make_float2(re1, im1);
        xc[(h0 + 32) * 16 + k] = make_float2(re2, im2);
        xc[(h0 + 48) * 16 + k] = make_float2(re3, im3);
    }
    __syncthreads();

    // ---- stage 5: forward H-DFT, 2 outputs/thread via i^{h&3} rotation ----
    {
        int k = tid & 15, mi0 = tid >> 4;     // mi0 in [0,16)
        int m0 = mi0;
        float2 acc0 = {0,0}, acc1 = {0,0};
#pragma unroll
        for (int hb = 0; hb < 64; hb += 4) {
#pragma unroll
            for (int j = 0; j < 4; j++) {
                int h = hb + j;
                float2 v = xc[h * 16 + k];
                float2 t = tw[(h * m0) & 63];
                float pr = v.x * t.x + v.y * t.y;   // v * e^{-i theta0}
                float pi = v.y * t.x - v.x * t.y;
                acc0.x += pr; acc0.y += pi;
                if (j == 0)      { acc1.x += pr; acc1.y += pi; }
                else if (j == 1) { acc1.x -= pi; acc1.y += pr; }
                else if (j == 2) { acc1.x -= pr; acc1.y -= pi; }
                else             { acc1.x += pi; acc1.y -= pr; }
            }
        }
        xft_out[(bo * 32 + mi0) * 16 + k] = acc0;
        xft_out[(bo * 32 + mi0 + 16) * 16 + k] = acc1;
    }
}

// ---------------- projection pass 1: 12 -> 256 gelu, q[p][k] fp16 ------------
__global__ void k_proj1(const float* __restrict__ p1w, const float* __restrict__ p1b) {
    __shared__ float w1s[12 * 256];
    __shared__ float b1s[256];
    int tid = threadIdx.x;
    int wid = tid >> 5, lid = tid & 31;
    if (tid < 256) b1s[tid] = p1b[tid];
    for (int i = tid; i < 12 * 256; i += 256) w1s[i] = p1w[i];
    __syncthreads();

    int p = blockIdx.x * 8 + wid;
    int b = p >> 12, hw = p & 4095;
    float tv[12];
#pragma unroll
    for (int c = 0; c < 12; c++) tv[c] = g_t0[(b * 12 + c) * HWSZ + hw];

#pragma unroll
    for (int r = 0; r < 2; r++) {
        int jb = r * 128 + lid * 4;
        float f[4];
#pragma unroll
        for (int jj = 0; jj < 4; jj++) {
            int j = jb + jj;
            float a = b1s[j];
#pragma unroll
            for (int c = 0; c < 12; c++) a = fmaf(tv[c], w1s[c * 256 + j], a);
            f[jj] = gelu_tab(a);
        }
        __half2 h01 = __floats2half2_rn(f[0], f[1]);
        __half2 h23 = __floats2half2_rn(f[2], f[3]);
        uint2 pk;
        pk.x = *(uint32_t*)&h01;
        pk.y = *(uint32_t*)&h23;
        *(uint2*)&g_q[(size_t)p * 256 + jb] = pk;
    }
}

// ---------------- projection pass 2: mma.sync fp16 GEMM 65536x640x256 --------
#define PADK 40        /* halves per smem row (80B), conflict-free */
#define STAGEH (2 * 128 * PADK)   /* halves per stage (A + B) */
#define NSTAGE 3

__device__ __forceinline__ void mma16n8k16(float* c, const uint32_t* a, const uint32_t* b) {
    asm volatile(
        "mma.sync.aligned.m16n8k16.row.col.f32.f16.f16.f32 "
        "{%0,%1,%2,%3}, {%4,%5,%6,%7}, {%8,%9}, {%0,%1,%2,%3};"
        : "+f"(c[0]), "+f"(c[1]), "+f"(c[2]), "+f"(c[3])
        : "r"(a[0]), "r"(a[1]), "r"(a[2]), "r"(a[3]), "r"(b[0]), "r"(b[1]));
}

__global__ __launch_bounds__(256, 2)
void k_gemm_mma(const float* __restrict__ p2b, float* __restrict__ out) {
    extern __shared__ __half smh[];
    __shared__ float sPb[128];
    int tid = threadIdx.x;
    int wid = tid >> 5, lane = tid & 31;
    int tig = lane & 3, grp = lane >> 2;
    int wm = wid & 1, wn = wid >> 1;         // warp tile: 64 rows x 32 cols
    int n0 = blockIdx.x * 128;
    int m0 = blockIdx.y * 128;
    if (tid < 128) sPb[tid] = p2b[n0 + tid];

    const __half* Aop = g_q + (size_t)m0 * 256;
    const __half* Bop = g_bt + (size_t)n0 * 256;

    float acc[4][4][4];
#pragma unroll
    for (int i = 0; i < 4; i++)
#pragma unroll
        for (int j = 0; j < 4; j++)
#pragma unroll
            for (int r = 0; r < 4; r++) acc[i][j][r] = 0.f;

#define PREFETCH(ch) do {                                                     \
    int st_ = (ch) % NSTAGE;                                                  \
    __half* Ab_ = smh + st_ * STAGEH;                                         \
    __half* Bb_ = Ab_ + 128 * PADK;                                           \
    int k0_ = (ch) * 32;                                                      \
    _Pragma("unroll")                                                         \
    for (int it = 0; it < 2; it++) {                                          \
        int fi = tid + it * 256;              /* 0..511 */                    \
        int row = fi >> 2, c8 = (fi & 3) * 8;                                 \
        uint32_t da = (uint32_t)__cvta_generic_to_shared(Ab_ + row * PADK + c8); \
        const __half* ga = Aop + (size_t)row * 256 + k0_ + c8;                \
        asm volatile("cp.async.cg.shared.global [%0], [%1], 16;" :: "r"(da), "l"(ga)); \
        uint32_t db = (uint32_t)__cvta_generic_to_shared(Bb_ + row * PADK + c8); \
        const __half* gb = Bop + (size_t)row * 256 + k0_ + c8;                \
        asm volatile("cp.async.cg.shared.global [%0], [%1], 16;" :: "r"(db), "l"(gb)); \
    }                                                                         \
    asm volatile("cp.async.commit_group;" ::: "memory");                      \
} while (0)

    PREFETCH(0);
    PREFETCH(1);

    for (int ch = 0; ch < 8; ch++) {
        if (ch < 7) {
            asm volatile("cp.async.wait_group 1;" ::: "memory");
        } else {
            asm volatile("cp.async.wait_group 0;" ::: "memory");
        }
        __syncthreads();
        const __half* Ab = smh + (ch % NSTAGE) * STAGEH;
        const __half* Bb = Ab + 128 * PADK;

#pragma unroll
        for (int kk = 0; kk < 2; kk++) {      // two k16 steps per 32-chunk
            int kb = kk * 16;
            uint32_t af[4][4], bf[4][2];
#pragma unroll
            for (int mt = 0; mt < 4; mt++) {
                int r0 = wm * 64 + mt * 16 + grp;
                af[mt][0] = *(const uint32_t*)&Ab[r0 * PADK + kb + tig * 2];
                af[mt][1] = *(const uint32_t*)&Ab[(r0 + 8) * PADK + kb + tig * 2];
                af[mt][2] = *(const uint32_t*)&Ab[r0 * PADK + kb + tig * 2 + 8];
                af[mt][3] = *(const uint32_t*)&Ab[(r0 + 8) * PADK + kb + tig * 2 + 8];
            }
#pragma unroll
            for (int nt = 0; nt < 4; nt++) {
                int e = wn * 32 + nt * 8 + grp;
                bf[nt][0] = *(const uint32_t*)&Bb[e * PADK + kb + tig * 2];
                bf[nt][1] = *(const uint32_t*)&Bb[e * PADK + kb + tig * 2 + 8];
            }
#pragma unroll
            for (int mt = 0; mt < 4; mt++)
#pragma unroll
                for (int nt = 0; nt < 4; nt++)
                    mma16n8k16(acc[mt][nt], af[mt], bf[nt]);
        }
        if (ch + 2 < 8) PREFETCH(ch + 2);
    }

    // epilogue: (acc + bias) * branch
    float br = g_branch[m0 >> 12];
#pragma unroll
    for (int mt = 0; mt < 4; mt++) {
        int row0 = m0 + wm * 64 + mt * 16 + grp;
        int row1 = row0 + 8;
        float* o0 = out + (size_t)(row0 >> 6) * (OUTC * 64) + (row0 & 63);
        float* o1 = out + (size_t)(row1 >> 6) * (OUTC * 64) + (row1 & 63);
#pragma unroll
        for (int nt = 0; nt < 4; nt++) {
            int el = wn * 32 + nt * 8 + 2 * tig;     // local e in [0,128)
            int e = n0 + el;
            float b0 = sPb[el], b1 = sPb[el + 1];
            __stcs(o0 + (size_t)e * 64,       (acc[mt][nt][0] + b0) * br);
            __stcs(o0 + (size_t)(e + 1) * 64, (acc[mt][nt][1] + b1) * br);
            __stcs(o1 + (size_t)e * 64,       (acc[mt][nt][2] + b0) * br);
            __stcs(o1 + (size_t)(e + 1) * 64, (acc[mt][nt][3] + b1) * br);
        }
    }
#undef PREFETCH
}

#define GEMM_SMEM (NSTAGE * STAGEH * 2)   /* 61440 bytes */

// ---------------- launch ------------------------------------------------------
extern "C" void kernel_launch(void* const* d_in, const int* in_sizes, int n_in,
                              void* d_out, int out_size) {
    const float* x     = (const float*)d_in[0];
    const float* cond  = (const float*)d_in[1];
    const float* bn2_g = (const float*)d_in[2];
    const float* bn2_b = (const float*)d_in[3];
    const float* bn1_g = (const float*)d_in[4];
    const float* bn1_b = (const float*)d_in[5];
    const float* b_w1  = (const float*)d_in[6];
    const float* b_b1  = (const float*)d_in[7];
    const float* b_w2  = (const float*)d_in[8];
    const float* b_b2  = (const float*)d_in[9];
    const float* b_w3  = (const float*)d_in[10];
    const float* b_b3  = (const float*)d_in[11];
    const float* l1_w  = (const float*)d_in[12];
    const float* l1_b  = (const float*)d_in[13];
    const float* l2_w  = (const float*)d_in[14];
    const float* l2_b  = (const float*)d_in[15];
    const float* sw1r  = (const float*)d_in[16];
    const float* sw1i  = (const float*)d_in[17];
    const float* sw2r  = (const float*)d_in[18];
    const float* sw2i  = (const float*)d_in[19];
    const float* sk_w  = (const float*)d_in[20];
    const float* sk_b  = (const float*)d_in[21];
    const float* p1_w  = (const float*)d_in[22];
    const float* p1_b  = (const float*)d_in[23];
    const float* p2_w  = (const float*)d_in[24];
    const float* p2_b  = (const float*)d_in[25];
    float* out = (float*)d_out;

    cudaFuncSetAttribute(k_gemm_mma, cudaFuncAttributeMaxDynamicSharedMemorySize, GEMM_SMEM);

    k_prolog<<<PRO_GRID, 512>>>(x, bn2_g, bn2_b, cond, bn1_g, bn1_b,
                                b_w1, b_b1, b_w2, b_b2, b_w3, b_b3,
                                l1_w, l1_b, l2_w, l2_b, p2_w);

    k_fwd0l<<<BB * HID, 512>>>(x);
    for (int lay = 0; lay < 4; lay++)
        k_layer<<<BB * HID, 256>>>(lay, sw1r, sw1i, sw2r, sw2i, sk_w, sk_b);

    k_proj1<<<NPIX / 8, 256>>>(p1_w, p1_b);

    dim3 gg(OUTC / 128, NPIX / 128);
    k_gemm_mma<<<gg, 256, GEMM_SMEM>>>(p2_b, out);
}

// round 15
// speedup vs baseline: 1.1003x; 1.0628x over previous
#include <cuda_runtime.h>
#include <cuda_fp16.h>
#include <math.h>
#include <stdint.h>

#define BB 16
#define HH 64
#define WW 64
#define HID 12
#define MODES 16
#define LIFTC 256
#define OUTC 640
#define NPIX (BB*HH*WW)      /* 65536 */
#define HWSZ (HH*WW)         /* 4096 */
#define EPS 1e-5f
#define TAB_N 8192
#define TAB_LO (-9.0f)
#define TAB_STEP (18.0f / TAB_N)
#define TAB_INV (TAB_N / 18.0f)
#define GT_N 8192            /* gelu table: [-8, 8], step 1/512 */

// ---------------- scratch (device globals; no allocations allowed) ----------
__device__ __align__(16) float2 g_tw[64];           // (cos, sin) interleaved
__device__ float g_scale, g_shift;
__device__ float g_branch[BB];
__device__ __align__(16) float g_t0[BB*HID*HWSZ];   // 3 MB ping
__device__ __align__(16) float g_t1[BB*HID*HWSZ];   // 3 MB pong
__device__ __align__(16) float2 g_xftA[BB*HID*32*MODES];  // spectrum ping
__device__ __align__(16) float2 g_xftB[BB*HID*32*MODES];  // spectrum pong
__device__ __align__(16) __half g_q[NPIX*LIFTC];          // 32 MB, [p][k], fp16
__device__ __align__(16) __half g_bt[OUTC*LIFTC];         // 320 KB, [e][k], fp16
__device__ __align__(16) float g_tab[12 * (TAB_N + 1)];   // lifting table, CHANNEL-major
__device__ __align__(16) float g_gt[GT_N + 1];            // gelu lookup table

__device__ __forceinline__ float gelu_exact(float x) { return x * normcdff(x); }

// table gelu: linear interp on [-8,8], exact tails
__device__ __forceinline__ float gelu_tab(float a) {
    float f = fmaf(a, 512.0f, 4096.0f);
    f = fminf(fmaxf(f, 0.0f), 8191.999f);
    int i = (int)f;
    float fr = f - (float)i;
    float a0 = g_gt[i], a1 = g_gt[i + 1];
    float g = fmaf(fr, a1 - a0, a0);
    return (a >= 8.0f) ? a : g;
}

// ---------------- combined prologue ------------------------------------------
#define PRO_TAB0 0
#define PRO_TRA0 129
#define PRO_SET0 289
#define PRO_STAT 306
#define PRO_BRAN 307
#define PRO_GRID 308

__global__ __launch_bounds__(512)
void k_prolog(const float* __restrict__ x,
              const float* __restrict__ bn2_g, const float* __restrict__ bn2_b,
              const float* __restrict__ cond,
              const float* __restrict__ g1, const float* __restrict__ b1,
              const float* __restrict__ w1, const float* __restrict__ bb1,
              const float* __restrict__ w2, const float* __restrict__ bb2,
              const float* __restrict__ w3, const float* __restrict__ bb3,
              const float* __restrict__ l1w, const float* __restrict__ l1b,
              const float* __restrict__ l2w, const float* __restrict__ l2b,
              const float* __restrict__ p2w) {
    __shared__ __align__(16) char shm[36864];
    int tid = threadIdx.x;
    int blk = blockIdx.x;

    if (blk < PRO_TRA0) {
        float* s1w = (float*)shm;
        float* s1b = s1w + 256;
        float* s2w = s1b + 256;
        float* s2b = s2w + 3072;
        float* red = s2b + 16;
        if (tid < 256) { s1w[tid] = l1w[tid]; s1b[tid] = l1b[tid]; }
        for (int i = tid; i < 256 * 12; i += 512) s2w[i] = l2w[i];
        if (tid >= 256 && tid < 268) s2b[tid - 256] = l2b[tid - 256];
        __syncthreads();

        int pl = tid & 63, qd = tid >> 6;
        int pt = blk * 64 + pl;
        float s = TAB_LO + (float)pt * TAB_STEP;
        float acc[12];
#pragma unroll
        for (int e = 0; e < 12; e++) acc[e] = 0.f;
        int d0 = qd * 32;
        for (int d = d0; d < d0 + 32; d++) {
            float u = fmaf(s, s1w[d], s1b[d]);
            float gl = gelu_exact(u);
#pragma unroll
            for (int e = 0; e < 12; e++) acc[e] = fmaf(gl, s2w[d * 12 + e], acc[e]);
        }
        if (qd > 0) {
#pragma unroll
            for (int e = 0; e < 12; e++) red[((qd - 1) * 64 + pl) * 12 + e] = acc[e];
        }
        __syncthreads();
        if (qd == 0 && pt <= TAB_N) {
            float r[12];
#pragma unroll
            for (int e = 0; e < 12; e++) r[e] = acc[e] + s2b[e];
#pragma unroll
            for (int g = 0; g < 7; g++)
#pragma unroll
                for (int e = 0; e < 12; e++) r[e] += red[(g * 64 + pl) * 12 + e];
#pragma unroll
            for (int e = 0; e < 12; e++) g_tab[e * (TAB_N + 1) + pt] = r[e];
        }
    } else if (blk < PRO_SET0) {
        float (*t)[33] = (float(*)[33])shm;
        int bx = blk - PRO_TRA0;
        int e0 = (bx % 20) * 32, k0 = (bx / 20) * 32;
        int tx = tid & 31, ty = tid >> 5;
#pragma unroll
        for (int r = 0; r < 2; r++)
            t[ty + r * 16][tx] = p2w[(k0 + ty + r * 16) * OUTC + e0 + tx];
        __syncthreads();
#pragma unroll
        for (int r = 0; r < 2; r++)
            g_bt[(e0 + ty + r * 16) * 256 + k0 + tx] = __float2half_rn(t[tx][ty + r * 16]);
    } else if (blk < PRO_STAT) {
        int sb = blk - PRO_SET0;
        if (sb == 0 && tid < 64) {
            float s, c;
            sincospif((float)tid / 32.0f, &s, &c);
            g_tw[tid] = make_float2(c, s);
        }
        int idx = sb * 512 + tid;
        if (idx <= GT_N) {
            float xx = -8.0f + (float)idx * (16.0f / GT_N);
            g_gt[idx] = gelu_exact(xx);
        }
    } else if (blk == PRO_STAT) {
        double* ssum = (double*)shm;
        double* ssq = ssum + 512;
        double s = 0.0, q = 0.0;
        const float4* x4 = (const float4*)x;
        for (int i = tid; i < NPIX / 4; i += 512) {
            float4 v = x4[i];
            s += (double)v.x + (double)v.y + (double)v.z + (double)v.w;
            q += (double)v.x * v.x + (double)v.y * v.y + (double)v.z * v.z + (double)v.w * v.w;
        }
        ssum[tid] = s; ssq[tid] = q;
        __syncthreads();
        for (int o = 256; o > 0; o >>= 1) {
            if (tid < o) { ssum[tid] += ssum[tid + o]; ssq[tid] += ssq[tid + o]; }
            __syncthreads();
        }
        if (tid == 0) {
            double m = ssum[0] / (double)NPIX;
            double var = ssq[0] / (double)NPIX - m * m;
            float rstd = rsqrtf((float)var + EPS);
            float sc = bn2_g[0] * rstd;
            g_scale = sc;
            g_shift = bn2_b[0] - (float)m * sc;
        }
    } else {
        float* w1s = (float*)shm;
        float* b1s = w1s + 104;
        float* w2s = b1s + 56;
        float* b2s = w2s + 2500;
        float* w3s = b2s + 52;
        float* b3s = w3s + 52;
        float* cs  = b3s + 3;
        float* cb  = cs + 2;
        float* h1s = cb + 2;
        int w = tid >> 5, lane = tid & 31;

        if (tid < 100) w1s[tid] = w1[tid];
        if (tid >= 128 && tid < 178) b1s[tid - 128] = bb1[tid - 128];
        if (tid >= 192 && tid < 242) b2s[tid - 192] = bb2[tid - 192];
        if (tid >= 256 && tid < 306) w3s[tid - 256] = w3[tid - 256];
        if (tid == 320) b3s[0] = bb3[0];
        for (int i = tid; i < 2500; i += 512) w2s[i] = w2[i];
        if (tid < 2) {
            float m = 0.f;
            for (int b = 0; b < BB; b++) m += cond[b * 2 + tid];
            m /= (float)BB;
            float v = 0.f;
            for (int b = 0; b < BB; b++) { float d = cond[b * 2 + tid] - m; v += d * d; }
            v /= (float)BB;
            float sc = rsqrtf(v + EPS) * g1[tid];
            cs[tid] = sc;
            cb[tid] = b1[tid] - m * sc;
        }
        __syncthreads();

        float c0 = cond[w * 2 + 0] * cs[0] + cb[0];
        float c1 = cond[w * 2 + 1] * cs[1] + cb[1];
        for (int j = lane; j < 50; j += 32)
            h1s[w * 52 + j] = tanhf(c0 * w1s[j] + c1 * w1s[50 + j] + b1s[j]);
        __syncwarp();

        float part = 0.f;
        for (int j = lane; j < 50; j += 32) {
            float a = b2s[j];
#pragma unroll 10
            for (int k = 0; k < 50; k++) a = fmaf(h1s[w * 52 + k], w2s[k * 50 + j], a);
            part += tanhf(a) * w3s[j];
        }
#pragma unroll
        for (int o = 16; o > 0; o >>= 1)
            part += __shfl_down_sync(0xffffffff, part, o);
        if (lane == 0) g_branch[w] = tanhf(part + b3s[0]);
    }
}

// ---------------- fused lift + forward DFT, block per (b,c) ------------------
__global__ __launch_bounds__(512)
void k_fwd0l(const float* __restrict__ x) {
    __shared__ float ts[4096];
    __shared__ float2 xc[64 * 16];   // [h][k]
    __shared__ float2 tw[64];
    int tid = threadIdx.x;
    int bc = blockIdx.x;
    int b = bc / 12, c = bc % 12;
    if (tid < 64) tw[tid] = g_tw[tid];

    const float* tabc = g_tab + c * (TAB_N + 1);
    float sc = g_scale, sh = g_shift;
#pragma unroll
    for (int i = 0; i < 8; i++) {
        int p = tid + i * 512;
        float s = fmaf(x[b * HWSZ + p], sc, sh);
        float f = (s - TAB_LO) * TAB_INV;
        f = fminf(fmaxf(f, 0.0f), (float)TAB_N - 0.0005f);
        int i0 = (int)f;
        float fr = f - (float)i0;
        float a = tabc[i0], bb2 = tabc[i0 + 1];
        float v = fmaf(fr, bb2 - a, a);
        ts[p] = v;
        g_t0[bc * HWSZ + p] = v;
    }
    __syncthreads();

#pragma unroll
    for (int r = 0; r < 2; r++) {
        int o = tid + r * 512;
        int h = o >> 4, k = o & 15;
        float re = 0.f, im = 0.f;
#pragma unroll 8
        for (int w = 0; w < 64; w++) {
            float2 t = tw[(w * k) & 63];
            float v = ts[h * 64 + w];
            re = fmaf(v, t.x, re);
            im = fmaf(-v, t.y, im);
        }
        xc[h * 16 + k] = make_float2(re, im);
    }
    __syncthreads();

    int mi = tid >> 4, k = tid & 15;
    int m = mi + (mi >= 16 ? 32 : 0);
    float re = 0.f, im = 0.f;
#pragma unroll 8
    for (int h = 0; h < 64; h++) {
        float2 t = tw[(h * m) & 63];
        float2 v = xc[h * 16 + k];
        re += v.x * t.x + v.y * t.y;   // * e^{-i theta}
        im += v.y * t.x - v.x * t.y;
    }
    g_xftA[(bc * 32 + mi) * 16 + k] = make_float2(re, im);
}

// ---------------- fused layer: spec + invH + invW/skip/gelu + fwdW + fwdH ----
// 256 threads/block; quarter-turn twiddle identity (round-12 proven form)
__global__ __launch_bounds__(256)
void k_layer(int lay,
             const float* __restrict__ sw1r, const float* __restrict__ sw1i,
             const float* __restrict__ sw2r, const float* __restrict__ sw2i,
             const float* __restrict__ skw_g, const float* __restrict__ skb_g) {
    const int in_flag = lay & 1;
    const float* tin = in_flag ? g_t1 : g_t0;
    float* tout = in_flag ? g_t0 : g_t1;
    const float2* xft_in = in_flag ? g_xftB : g_xftA;
    float2* xft_out = in_flag ? g_xftA : g_xftB;

    __shared__ float2 sy[32 * 16];     // spec output  [mi][k]
    __shared__ float2 Ys[64 * 16];     // invH output  [h][k]
    __shared__ float ts[4096];         // spatial field
    __shared__ float2 xc[64 * 16];     // fwdW output  [h][k]
    __shared__ float2 tw[64];
    __shared__ float skw[12];
    __shared__ float skb;

    int tid = threadIdx.x;
    int bo = blockIdx.x;
    int b = bo / 12, o = bo % 12;
    if (tid < 64) tw[tid] = g_tw[tid];
    if (tid >= 64 && tid < 76) skw[tid - 64] = skw_g[((lay * 12 + (tid - 64)) * 12) + o];
    if (tid == 76) skb = skb_g[lay * 12 + o];

    // ---- stage 1: spectral mix (2 outputs per thread) ----
#pragma unroll
    for (int r = 0; r < 2; r++) {
        int idx = tid + r * 256;
        int k = idx & 15, mi = idx >> 4;
        const float* wr = (mi < 16) ? sw1r : sw2r;
        const float* wi = (mi < 16) ? sw1i : sw2i;
        int mr = (mi < 16) ? mi : mi - 16;
        float yr = 0.f, yi = 0.f;
#pragma unroll
        for (int c = 0; c < 12; c++) {
            float2 xv = xft_in[((b * 12 + c) * 32 + mi) * 16 + k];
            int off = (((lay * 12 + c) * 12 + o) * 16 + mr) * 16 + k;
            float wre = wr[off], wim = wi[off];
            yr += xv.x * wre - xv.y * wim;
            yi += xv.x * wim + xv.y * wre;
        }
        sy[idx] = make_float2(yr, yi);
    }
    __syncthreads();

    // ---- stage 2: inverse H-DFT, 4 outputs/thread via i^q rotations ----
    {
        int k = tid & 15, h0 = tid >> 4;       // h0 in [0,16)
        float2 acc0 = {0,0}, acc1 = {0,0}, acc2 = {0,0}, acc3 = {0,0};
#pragma unroll
        for (int mib = 0; mib < 32; mib += 4) {
#pragma unroll
            for (int j = 0; j < 4; j++) {
                int mi = mib + j;
                int m = mi + (mi >= 16 ? 32 : 0);
                float2 v = sy[mi * 16 + k];
                float2 t = tw[(h0 * m) & 63];
                float pr = v.x * t.x - v.y * t.y;   // v * e^{+i theta0}
                float pi = v.x * t.y + v.y * t.x;
                acc0.x += pr; acc0.y += pi;
                if (j == 0) {
                    acc1.x += pr; acc1.y += pi;
                    acc2.x += pr; acc2.y += pi;
                    acc3.x += pr; acc3.y += pi;
                } else if (j == 1) {                 // q = r
                    acc1.x -= pi; acc1.y += pr;
                    acc2.x -= pr; acc2.y -= pi;
                    acc3.x += pi; acc3.y -= pr;
                } else if (j == 2) {                 // q = 2r & 3
                    acc1.x -= pr; acc1.y -= pi;
                    acc2.x += pr; acc2.y += pi;
                    acc3.x -= pr; acc3.y -= pi;
                } else {                             // q = 3r & 3
                    acc1.x += pi; acc1.y -= pr;
                    acc2.x -= pr; acc2.y -= pi;
                    acc3.x -= pi; acc3.y += pr;
                }
            }
        }
        Ys[h0 * 16 + k] = acc0;
        Ys[(h0 + 16) * 16 + k] = acc1;
        Ys[(h0 + 32) * 16 + k] = acc2;
        Ys[(h0 + 48) * 16 + k] = acc3;
    }
    __syncthreads();

    // ---- stage 3: inverse W-DFT + skip conv (+ gelu), 16 px per thread ----
    {
        int w = tid & 63, hg = tid >> 6;   // hg in [0,4)
        float2 twk[15];
#pragma unroll
        for (int k = 1; k < 16; k++) twk[k - 1] = tw[(w * k) & 63];
#pragma unroll 2
        for (int i = 0; i < 16; i++) {
            int h = hg * 16 + i;
            const float2* yr = &Ys[h * 16];
            float v = yr[0].x;    // k=0: imaginary part discarded by irfft
#pragma unroll
            for (int k = 1; k < 16; k++)
                v += 2.f * (yr[k].x * twk[k - 1].x - yr[k].y * twk[k - 1].y);
            v *= (1.0f / 4096.0f);
            float sk = skb;
#pragma unroll
            for (int c = 0; c < 12; c++)
                sk = fmaf(tin[(b * 12 + c) * HWSZ + h * 64 + w], skw[c], sk);
            float rres = v + sk;
            if (lay < 3) rres = gelu_tab(rres);
            ts[h * 64 + w] = rres;
            tout[(b * 12 + o) * HWSZ + h * 64 + w] = rres;
        }
    }
    if (lay == 3) return;
    __syncthreads();

    // ---- stage 4: forward W-DFT, 4 outputs/thread sharing twiddles ----
    {
        int k = tid & 15, h0 = tid >> 4;
        float re0 = 0, im0 = 0, re1 = 0, im1 = 0, re2 = 0, im2 = 0, re3 = 0, im3 = 0;
#pragma unroll 8
        for (int w = 0; w < 64; w++) {
            float2 t = tw[(w * k) & 63];
            float v0 = ts[h0 * 64 + w];
            float v1 = ts[(h0 + 16) * 64 + w];
            float v2 = ts[(h0 + 32) * 64 + w];
            float v3 = ts[(h0 + 48) * 64 + w];
            re0 = fmaf(v0, t.x, re0); im0 = fmaf(-v0, t.y, im0);
            re1 = fmaf(v1, t.x, re1); im1 = fmaf(-v1, t.y, im1);
            re2 = fmaf(v2, t.x, re2); im2 = fmaf(-v2, t.y, im2);
            re3 = fmaf(v3, t.x, re3); im3 = fmaf(-v3, t.y, im3);
        }
        xc[h0 * 16 + k] = make_float2(re0, im0);
        xc[(h0 + 16) * 16 + k] = make_float2(re1, im1);
        xc[(h0 + 32) * 16 + k] = make_float2(re2, im2);
        xc[(h0 + 48) * 16 + k] = make_float2(re3, im3);
    }
    __syncthreads();

    // ---- stage 5: forward H-DFT, 2 outputs/thread via i^{h&3} rotation ----
    {
        int k = tid & 15, mi0 = tid >> 4;     // mi0 in [0,16)
        int m0 = mi0;
        float2 acc0 = {0,0}, acc1 = {0,0};
#pragma unroll
        for (int hb = 0; hb < 64; hb += 4) {
#pragma unroll
            for (int j = 0; j < 4; j++) {
                int h = hb + j;
                float2 v = xc[h * 16 + k];
                float2 t = tw[(h * m0) & 63];
                float pr = v.x * t.x + v.y * t.y;   // v * e^{-i theta0}
                float pi = v.y * t.x - v.x * t.y;
                acc0.x += pr; acc0.y += pi;
                if (j == 0)      { acc1.x += pr; acc1.y += pi; }
                else if (j == 1) { acc1.x -= pi; acc1.y += pr; }
                else if (j == 2) { acc1.x -= pr; acc1.y -= pi; }
                else             { acc1.x += pi; acc1.y -= pr; }
            }
        }
        xft_out[(bo * 32 + mi0) * 16 + k] = acc0;
        xft_out[(bo * 32 + mi0 + 16) * 16 + k] = acc1;
    }
}

// ---------------- projection pass 1: 12 -> 256 gelu, q[p][k] fp16 ------------
__global__ void k_proj1(const float* __restrict__ p1w, const float* __restrict__ p1b) {
    __shared__ float w1s[12 * 256];
    __shared__ float b1s[256];
    int tid = threadIdx.x;
    int wid = tid >> 5, lid = tid & 31;
    if (tid < 256) b1s[tid] = p1b[tid];
    for (int i = tid; i < 12 * 256; i += 256) w1s[i] = p1w[i];
    __syncthreads();

    int p = blockIdx.x * 8 + wid;
    int b = p >> 12, hw = p & 4095;
    float tv[12];
#pragma unroll
    for (int c = 0; c < 12; c++) tv[c] = g_t0[(b * 12 + c) * HWSZ + hw];

#pragma unroll
    for (int r = 0; r < 2; r++) {
        int jb = r * 128 + lid * 4;
        float f[4];
#pragma unroll
        for (int jj = 0; jj < 4; jj++) {
            int j = jb + jj;
            float a = b1s[j];
#pragma unroll
            for (int c = 0; c < 12; c++) a = fmaf(tv[c], w1s[c * 256 + j], a);
            f[jj] = gelu_tab(a);
        }
        __half2 h01 = __floats2half2_rn(f[0], f[1]);
        __half2 h23 = __floats2half2_rn(f[2], f[3]);
        uint2 pk;
        pk.x = *(uint32_t*)&h01;
        pk.y = *(uint32_t*)&h23;
        *(uint2*)&g_q[(size_t)p * 256 + jb] = pk;
    }
}

// ---------------- projection pass 2: mma.sync fp16 GEMM + ldmatrix ----------
#define PADK 40        /* halves per smem row (80B), conflict-free */
#define STAGEH (2 * 128 * PADK)   /* halves per stage (A + B) */
#define NSTAGE 3

__device__ __forceinline__ void mma16n8k16(float* c, const uint32_t* a, const uint32_t* b) {
    asm volatile(
        "mma.sync.aligned.m16n8k16.row.col.f32.f16.f16.f32 "
        "{%0,%1,%2,%3}, {%4,%5,%6,%7}, {%8,%9}, {%0,%1,%2,%3};"
        : "+f"(c[0]), "+f"(c[1]), "+f"(c[2]), "+f"(c[3])
        : "r"(a[0]), "r"(a[1]), "r"(a[2]), "r"(a[3]), "r"(b[0]), "r"(b[1]));
}

__global__ __launch_bounds__(256, 2)
void k_gemm_mma(const float* __restrict__ p2b, float* __restrict__ out) {
    extern __shared__ __half smh[];
    __shared__ float sPb[128];
    int tid = threadIdx.x;
    int wid = tid >> 5, lane = tid & 31;
    int tig = lane & 3, grp = lane >> 2;
    int wm = wid & 1, wn = wid >> 1;         // warp tile: 64 rows x 32 cols
    int n0 = blockIdx.x * 128;
    int m0 = blockIdx.y * 128;
    if (tid < 128) sPb[tid] = p2b[n0 + tid];

    const __half* Aop = g_q + (size_t)m0 * 256;
    const __half* Bop = g_bt + (size_t)n0 * 256;

    // ldmatrix lane offsets (bytes):
    // A x4: lanes 0-15 -> rows (lane&15) @ k lo8; lanes 16-31 -> same rows @ k hi8
    uint32_t a_loff = (uint32_t)(((lane & 15) * PADK + (lane >> 4) * 8) * 2);
    // B x4: quad = lane>>3: row (lane&7) + (quad>>1)*8, k half = quad&1
    uint32_t b_loff = (uint32_t)((((lane & 7) + ((lane >> 4) & 1) * 8) * PADK
                                  + ((lane >> 3) & 1) * 8) * 2);

    float acc[4][4][4];
#pragma unroll
    for (int i = 0; i < 4; i++)
#pragma unroll
        for (int j = 0; j < 4; j++)
#pragma unroll
            for (int r = 0; r < 4; r++) acc[i][j][r] = 0.f;

#define PREFETCH(ch) do {                                                     \
    int st_ = (ch) % NSTAGE;                                                  \
    __half* Ab_ = smh + st_ * STAGEH;                                         \
    __half* Bb_ = Ab_ + 128 * PADK;                                           \
    int k0_ = (ch) * 32;                                                      \
    _Pragma("unroll")                                                         \
    for (int it = 0; it < 2; it++) {                                          \
        int fi = tid + it * 256;              /* 0..511 */                    \
        int row = fi >> 2, c8 = (fi & 3) * 8;                                 \
        uint32_t da = (uint32_t)__cvta_generic_to_shared(Ab_ + row * PADK + c8); \
        const __half* ga = Aop + (size_t)row * 256 + k0_ + c8;                \
        asm volatile("cp.async.cg.shared.global [%0], [%1], 16;" :: "r"(da), "l"(ga)); \
        uint32_t db = (uint32_t)__cvta_generic_to_shared(Bb_ + row * PADK + c8); \
        const __half* gb = Bop + (size_t)row * 256 + k0_ + c8;                \
        asm volatile("cp.async.cg.shared.global [%0], [%1], 16;" :: "r"(db), "l"(gb)); \
    }                                                                         \
    asm volatile("cp.async.commit_group;" ::: "memory");                      \
} while (0)

    PREFETCH(0);
    PREFETCH(1);

    for (int ch = 0; ch < 8; ch++) {
        if (ch < 7) {
            asm volatile("cp.async.wait_group 1;" ::: "memory");
        } else {
            asm volatile("cp.async.wait_group 0;" ::: "memory");
        }
        __syncthreads();
        const __half* Ab = smh + (ch % NSTAGE) * STAGEH;
        const __half* Bb = Ab + 128 * PADK;
        uint32_t abase = (uint32_t)__cvta_generic_to_shared(Ab) + a_loff;
        uint32_t bbase = (uint32_t)__cvta_generic_to_shared(Bb) + b_loff;

#pragma unroll
        for (int kk = 0; kk < 2; kk++) {      // two k16 steps per 32-chunk
            uint32_t kb2 = (uint32_t)(kk * 32);   // 16 halves = 32 bytes
            uint32_t af[4][4], bf[4][2];
#pragma unroll
            for (int mt = 0; mt < 4; mt++) {
                uint32_t ad = abase + (uint32_t)(((wm * 64 + mt * 16) * PADK) * 2) + kb2;
                asm volatile(
                    "ldmatrix.sync.aligned.m8n8.x4.shared.b16 {%0,%1,%2,%3}, [%4];"
                    : "=r"(af[mt][0]), "=r"(af[mt][1]), "=r"(af[mt][2]), "=r"(af[mt][3])
                    : "r"(ad));
            }
#pragma unroll
            for (int np = 0; np < 2; np++) {
                uint32_t bd = bbase + (uint32_t)(((wn * 32 + np * 16) * PADK) * 2) + kb2;
                asm volatile(
                    "ldmatrix.sync.aligned.m8n8.x4.shared.b16 {%0,%1,%2,%3}, [%4];"
                    : "=r"(bf[np * 2][0]), "=r"(bf[np * 2][1]),
                      "=r"(bf[np * 2 + 1][0]), "=r"(bf[np * 2 + 1][1])
                    : "r"(bd));
            }
#pragma unroll
            for (int mt = 0; mt < 4; mt++)
#pragma unroll
                for (int nt = 0; nt < 4; nt++)
                    mma16n8k16(acc[mt][nt], af[mt], bf[nt]);
        }
        if (ch + 2 < 8) PREFETCH(ch + 2);
    }

    // epilogue: (acc + bias) * branch
    float br = g_branch[m0 >> 12];
#pragma unroll
    for (int mt = 0; mt < 4; mt++) {
        int row0 = m0 + wm * 64 + mt * 16 + grp;
        int row1 = row0 + 8;
        float* o0 = out + (size_t)(row0 >> 6) * (OUTC * 64) + (row0 & 63);
        float* o1 = out + (size_t)(row1 >> 6) * (OUTC * 64) + (row1 & 63);
#pragma unroll
        for (int nt = 0; nt < 4; nt++) {
            int el = wn * 32 + nt * 8 + 2 * tig;     // local e in [0,128)
            int e = n0 + el;
            float b0 = sPb[el], b1 = sPb[el + 1];
            __stcs(o0 + (size_t)e * 64,       (acc[mt][nt][0] + b0) * br);
            __stcs(o0 + (size_t)(e + 1) * 64, (acc[mt][nt][1] + b1) * br);
            __stcs(o1 + (size_t)e * 64,       (acc[mt][nt][2] + b0) * br);
            __stcs(o1 + (size_t)(e + 1) * 64, (acc[mt][nt][3] + b1) * br);
        }
    }
#undef PREFETCH
}

#define GEMM_SMEM (NSTAGE * STAGEH * 2)   /* 61440 bytes */

// ---------------- launch ------------------------------------------------------
extern "C" void kernel_launch(void* const* d_in, const int* in_sizes, int n_in,
                              void* d_out, int out_size) {
    const float* x     = (const float*)d_in[0];
    const float* cond  = (const float*)d_in[1];
    const float* bn2_g = (const float*)d_in[2];
    const float* bn2_b = (const float*)d_in[3];
    const float* bn1_g = (const float*)d_in[4];
    const float* bn1_b = (const float*)d_in[5];
    const float* b_w1  = (const float*)d_in[6];
    const float* b_b1  = (const float*)d_in[7];
    const float* b_w2  = (const float*)d_in[8];
    const float* b_b2  = (const float*)d_in[9];
    const float* b_w3  = (const float*)d_in[10];
    const float* b_b3  = (const float*)d_in[11];
    const float* l1_w  = (const float*)d_in[12];
    const float* l1_b  = (const float*)d_in[13];
    const float* l2_w  = (const float*)d_in[14];
    const float* l2_b  = (const float*)d_in[15];
    const float* sw1r  = (const float*)d_in[16];
    const float* sw1i  = (const float*)d_in[17];
    const float* sw2r  = (const float*)d_in[18];
    const float* sw2i  = (const float*)d_in[19];
    const float* sk_w  = (const float*)d_in[20];
    const float* sk_b  = (const float*)d_in[21];
    const float* p1_w  = (const float*)d_in[22];
    const float* p1_b  = (const float*)d_in[23];
    const float* p2_w  = (const float*)d_in[24];
    const float* p2_b  = (const float*)d_in[25];
    float* out = (float*)d_out;

    cudaFuncSetAttribute(k_gemm_mma, cudaFuncAttributeMaxDynamicSharedMemorySize, GEMM_SMEM);

    k_prolog<<<PRO_GRID, 512>>>(x, bn2_g, bn2_b, cond, bn1_g, bn1_b,
                                b_w1, b_b1, b_w2, b_b2, b_w3, b_b3,
                                l1_w, l1_b, l2_w, l2_b, p2_w);

    k_fwd0l<<<BB * HID, 512>>>(x);
    for (int lay = 0; lay < 4; lay++)
        k_layer<<<BB * HID, 256>>>(lay, sw1r, sw1i, sw2r, sw2i, sk_w, sk_b);

    k_proj1<<<NPIX / 8, 256>>>(p1_w, p1_b);

    dim3 gg(OUTC / 128, NPIX / 128);
    k_gemm_mma<<<gg, 256, GEMM_SMEM>>>(p2_b, out);
}